// round 1
// baseline (speedup 1.0000x reference)
#include <cuda_runtime.h>
#include <cuda_bf16.h>

// TensorRepsTransform: per row n
//   out[0:64)    = t[0:64)                                  (order-0, even)
//   out[64+4s+j) = sign(det L) * sum_k L[j][k] t[64+4s+k]   (order-1, odd), s in [0,64)
//   out[320+16s+4j1+j2) = sum_{k1,k2} L[j1][k1] L[j2][k2] t[320+16s+4k1+k2]
//                                                           (order-2, even), s in [0,32)
// One warp per row. All accesses float4 (row stride 832 floats = 16B aligned).

#define ROW_DIM 832

__global__ __launch_bounds__(256) void trep_kernel(
    const float* __restrict__ tens,
    const float* __restrict__ lfr,
    float* __restrict__ out,
    int nrows)
{
    const int gwarp = (int)((blockIdx.x * 256u + threadIdx.x) >> 5);
    const int lane  = threadIdx.x & 31;
    if (gwarp >= nrows) return;

    const float* __restrict__ tr = tens + (size_t)gwarp * ROW_DIM;
    float* __restrict__       orow = out + (size_t)gwarp * ROW_DIM;

    // Load L (warp-uniform address -> broadcast)
    const float4* Lp = (const float4*)(lfr + (size_t)gwarp * 16);
    float4 r0 = Lp[0], r1 = Lp[1], r2 = Lp[2], r3 = Lp[3];
    float L[4][4] = {
        {r0.x, r0.y, r0.z, r0.w},
        {r1.x, r1.y, r1.z, r1.w},
        {r2.x, r2.y, r2.z, r2.w},
        {r3.x, r3.y, r3.z, r3.w}};

    // det(L) via 2x2 minor expansion
    float s0 = L[0][0]*L[1][1] - L[0][1]*L[1][0];
    float s1 = L[0][0]*L[1][2] - L[0][2]*L[1][0];
    float s2 = L[0][0]*L[1][3] - L[0][3]*L[1][0];
    float s3 = L[0][1]*L[1][2] - L[0][2]*L[1][1];
    float s4 = L[0][1]*L[1][3] - L[0][3]*L[1][1];
    float s5 = L[0][2]*L[1][3] - L[0][3]*L[1][2];
    float c5 = L[2][2]*L[3][3] - L[2][3]*L[3][2];
    float c4 = L[2][1]*L[3][3] - L[2][3]*L[3][1];
    float c3 = L[2][1]*L[3][2] - L[2][2]*L[3][1];
    float c2 = L[2][0]*L[3][3] - L[2][3]*L[3][0];
    float c1 = L[2][0]*L[3][2] - L[2][2]*L[3][0];
    float c0 = L[2][0]*L[3][1] - L[2][1]*L[3][0];
    float det = s0*c5 - s1*c4 + s2*c3 + s3*c2 - s4*c1 + s5*c0;
    float sgn = (det > 0.0f) ? 1.0f : ((det < 0.0f) ? -1.0f : 0.0f);

    // ---- order-0: copy 64 floats (16 float4, lanes 0..15) ----
    if (lane < 16) {
        ((float4*)orow)[lane] = ((const float4*)tr)[lane];
    }

    // ---- order-1: 64 slots, 2 per lane; y = sgn * L v ----
    #pragma unroll
    for (int i = 0; i < 2; i++) {
        int s = lane + 32 * i;
        float4 v = *(const float4*)(tr + 64 + 4 * s);
        float4 y;
        y.x = sgn * (L[0][0]*v.x + L[0][1]*v.y + L[0][2]*v.z + L[0][3]*v.w);
        y.y = sgn * (L[1][0]*v.x + L[1][1]*v.y + L[1][2]*v.z + L[1][3]*v.w);
        y.z = sgn * (L[2][0]*v.x + L[2][1]*v.y + L[2][2]*v.z + L[2][3]*v.w);
        y.w = sgn * (L[3][0]*v.x + L[3][1]*v.y + L[3][2]*v.z + L[3][3]*v.w);
        *(float4*)(orow + 64 + 4 * s) = y;
    }

    // ---- order-2: 32 slots, 1 per lane; U = L T L^T ----
    {
        const float* Tp = tr + 320 + 16 * lane;
        float T[4][4];
        #pragma unroll
        for (int a = 0; a < 4; a++) {
            float4 v = *(const float4*)(Tp + 4 * a);
            T[a][0] = v.x; T[a][1] = v.y; T[a][2] = v.z; T[a][3] = v.w;
        }
        // A = L * T  (contract first Lorentz index, as the reference does first)
        float A[4][4];
        #pragma unroll
        for (int j = 0; j < 4; j++) {
            #pragma unroll
            for (int m = 0; m < 4; m++) {
                A[j][m] = L[j][0]*T[0][m] + L[j][1]*T[1][m]
                        + L[j][2]*T[2][m] + L[j][3]*T[3][m];
            }
        }
        // U = A * L^T  (contract second Lorentz index)
        float* op = orow + 320 + 16 * lane;
        #pragma unroll
        for (int j = 0; j < 4; j++) {
            float4 u;
            u.x = A[j][0]*L[0][0] + A[j][1]*L[0][1] + A[j][2]*L[0][2] + A[j][3]*L[0][3];
            u.y = A[j][0]*L[1][0] + A[j][1]*L[1][1] + A[j][2]*L[1][2] + A[j][3]*L[1][3];
            u.z = A[j][0]*L[2][0] + A[j][1]*L[2][1] + A[j][2]*L[2][2] + A[j][3]*L[2][3];
            u.w = A[j][0]*L[3][0] + A[j][1]*L[3][1] + A[j][2]*L[3][2] + A[j][3]*L[3][3];
            *(float4*)(op + 4 * j) = u;
        }
    }
}

extern "C" void kernel_launch(void* const* d_in, const int* in_sizes, int n_in,
                              void* d_out, int out_size)
{
    const float* tens = (const float*)d_in[0];   // (N, 832) float32
    const float* lfr  = (const float*)d_in[1];   // (N, 4, 4) float32
    // d_in[2] = parity_odd mask: compile-time constant of REPS, folded into layout.
    (void)n_in;

    int nrows = in_sizes[0] / ROW_DIM;           // 65536
    float* out = (float*)d_out;

    // one warp per row, 8 warps (256 threads) per block
    int nwarps  = nrows;
    int nblocks = (nwarps * 32 + 255) / 256;
    trep_kernel<<<nblocks, 256>>>(tens, lfr, out, nrows);
}

// round 2
// speedup vs baseline: 1.0271x; 1.0271x over previous
#include <cuda_runtime.h>
#include <cuda_bf16.h>

// TensorRepsTransform: per row n (N=65536, DIM=832)
//   out[0:64)         = t[0:64)                                   (order-0, even)
//   out[64+4s+j)      = sign(det L) * sum_k L[j][k] t[64+4s+k]    (order-1, odd), s in [0,64)
//   out[320+16s+4a+b) = sum_{k1,k2} L[a][k1] L[b][k2] t[320+16s+4k1+4k2]  (order-2, even)
//
// One warp per row. ALL global accesses are coalesced float4 (each LDG/STG.128
// covers 4 consecutive cache lines, 100% sectors). Order-2 rows are exchanged
// inside 4-lane groups via width-4 shuffles.

#define ROW_DIM 832

__global__ __launch_bounds__(256) void trep_kernel(
    const float* __restrict__ tens,
    const float* __restrict__ lfr,
    float* __restrict__ out,
    int nrows)
{
    const int gwarp = (int)((blockIdx.x * 256u + threadIdx.x) >> 5);
    const int lane  = threadIdx.x & 31;
    if (gwarp >= nrows) return;

    const float* __restrict__ tr   = tens + (size_t)gwarp * ROW_DIM;
    float* __restrict__       orow = out  + (size_t)gwarp * ROW_DIM;

    // ---- front-batched loads (max MLP) ----
    // L: warp-uniform address -> broadcast
    const float4* Lp = (const float4*)(lfr + (size_t)gwarp * 16);
    float4 Lr0 = Lp[0], Lr1 = Lp[1], Lr2 = Lp[2], Lr3 = Lp[3];

    // order-0: 16 float4, lanes 0..15
    float4 q0;
    if (lane < 16) q0 = __ldcs(((const float4*)tr) + lane);

    // order-1: 64 float4, 2 per lane (coalesced)
    float4 v1 = __ldcs(((const float4*)(tr + 64)) + lane);
    float4 v2 = __ldcs(((const float4*)(tr + 64)) + lane + 32);

    // order-2: 128 float4, 4 per lane (coalesced); iteration a -> float4 #(32a+lane)
    float4 t0 = __ldcs(((const float4*)(tr + 320)) + lane);
    float4 t1 = __ldcs(((const float4*)(tr + 320)) + lane + 32);
    float4 t2 = __ldcs(((const float4*)(tr + 320)) + lane + 64);
    float4 t3 = __ldcs(((const float4*)(tr + 320)) + lane + 96);

    // ---- det(L) sign (per-lane, uniform within warp) ----
    float L00=Lr0.x, L01=Lr0.y, L02=Lr0.z, L03=Lr0.w;
    float L10=Lr1.x, L11=Lr1.y, L12=Lr1.z, L13=Lr1.w;
    float L20=Lr2.x, L21=Lr2.y, L22=Lr2.z, L23=Lr2.w;
    float L30=Lr3.x, L31=Lr3.y, L32=Lr3.z, L33=Lr3.w;

    float s0 = L00*L11 - L01*L10;
    float s1 = L00*L12 - L02*L10;
    float s2 = L00*L13 - L03*L10;
    float s3 = L01*L12 - L02*L11;
    float s4 = L01*L13 - L03*L11;
    float s5 = L02*L13 - L03*L12;
    float c5 = L22*L33 - L23*L32;
    float c4 = L21*L33 - L23*L31;
    float c3 = L21*L32 - L22*L31;
    float c2 = L20*L33 - L23*L30;
    float c1 = L20*L32 - L22*L30;
    float c0 = L20*L31 - L21*L30;
    float det = s0*c5 - s1*c4 + s2*c3 + s3*c2 - s4*c1 + s5*c0;
    float sgn = (det > 0.0f) ? 1.0f : ((det < 0.0f) ? -1.0f : 0.0f);

    // ---- order-0: passthrough ----
    if (lane < 16) __stcs(((float4*)orow) + lane, q0);

    // ---- order-1: y = sgn * (L v), 2 slots per lane ----
    {
        float4 y;
        y.x = sgn * (L00*v1.x + L01*v1.y + L02*v1.z + L03*v1.w);
        y.y = sgn * (L10*v1.x + L11*v1.y + L12*v1.z + L13*v1.w);
        y.z = sgn * (L20*v1.x + L21*v1.y + L22*v1.z + L23*v1.w);
        y.w = sgn * (L30*v1.x + L31*v1.y + L32*v1.z + L33*v1.w);
        __stcs(((float4*)(orow + 64)) + lane, y);

        y.x = sgn * (L00*v2.x + L01*v2.y + L02*v2.z + L03*v2.w);
        y.y = sgn * (L10*v2.x + L11*v2.y + L12*v2.z + L13*v2.w);
        y.z = sgn * (L20*v2.x + L21*v2.y + L22*v2.z + L23*v2.w);
        y.w = sgn * (L30*v2.x + L31*v2.y + L32*v2.z + L33*v2.w);
        __stcs(((float4*)(orow + 64)) + lane + 32, y);
    }

    // ---- order-2: U = L (T L^T), cooperative in 4-lane groups ----
    // Lane holds T[r][*] with r = lane&3 of slot (8a + lane>>2).
    // B = T_row . L^T  (B[m] = sum_k L[m][k] T[r][k]), local.
    // U[r][m] = sum_{r'} L[r][r'] * B_{r'}[m], via width-4 shuffles.
    const int r = lane & 3;
    // L row r selected once (compile-time-unrollable component access afterwards)
    float4 Lrow = (r == 0) ? Lr0 : (r == 1) ? Lr1 : (r == 2) ? Lr2 : Lr3;

    #pragma unroll
    for (int a = 0; a < 4; a++) {
        float4 Ta = (a == 0) ? t0 : (a == 1) ? t1 : (a == 2) ? t2 : t3;

        float4 B;
        B.x = L00*Ta.x + L01*Ta.y + L02*Ta.z + L03*Ta.w;
        B.y = L10*Ta.x + L11*Ta.y + L12*Ta.z + L13*Ta.w;
        B.z = L20*Ta.x + L21*Ta.y + L22*Ta.z + L23*Ta.w;
        B.w = L30*Ta.x + L31*Ta.y + L32*Ta.z + L33*Ta.w;

        float4 U = make_float4(0.f, 0.f, 0.f, 0.f);
        #pragma unroll
        for (int rp = 0; rp < 4; rp++) {
            float bx = __shfl_sync(0xffffffffu, B.x, rp, 4);
            float by = __shfl_sync(0xffffffffu, B.y, rp, 4);
            float bz = __shfl_sync(0xffffffffu, B.z, rp, 4);
            float bw = __shfl_sync(0xffffffffu, B.w, rp, 4);
            float c = (rp == 0) ? Lrow.x : (rp == 1) ? Lrow.y
                    : (rp == 2) ? Lrow.z : Lrow.w;
            U.x += c * bx;
            U.y += c * by;
            U.z += c * bz;
            U.w += c * bw;
        }
        __stcs(((float4*)(orow + 320)) + 32 * a + lane, U);
    }
}

extern "C" void kernel_launch(void* const* d_in, const int* in_sizes, int n_in,
                              void* d_out, int out_size)
{
    const float* tens = (const float*)d_in[0];   // (N, 832) float32
    const float* lfr  = (const float*)d_in[1];   // (N, 4, 4) float32
    // d_in[2] = parity_odd mask: compile-time constant of REPS, folded into layout.
    (void)n_in; (void)out_size;

    int nrows = in_sizes[0] / ROW_DIM;           // 65536
    float* out = (float*)d_out;

    int nblocks = (nrows * 32 + 255) / 256;      // one warp per row
    trep_kernel<<<nblocks, 256>>>(tens, lfr, out, nrows);
}